// round 2
// baseline (speedup 1.0000x reference)
#include <cuda_runtime.h>
#include <math.h>

#define BB 2
#define SS 2048
#define DD 1024
#define HH 16
#define MROWS (BB*SS)   // 4096

// ---------------- scratch (no cudaMalloc allowed) ----------------
__device__ float g_qkv[(size_t)MROWS * 3072];
__device__ float g_attn[(size_t)MROWS * DD];
__device__ float g_y[(size_t)MROWS * DD];
__device__ int   g_mask_mode;  // 0=int32, 1=uint8, 2=float32
__device__ __align__(8) unsigned int g_maskbits[(size_t)BB * SS * SS / 32];

// ---------------- mask dtype detection ----------------
// int32 bools -> words in {0,1}; uint8 bools -> words with nonzero bytes 1..3
// (~59% of words at 20% density); float32 bools -> words in {0, 0x3F800000}.
__global__ void detect_mask_kernel(const unsigned int* __restrict__ m)
{
    __shared__ int sfloat, shigh;
    if (threadIdx.x == 0) { sfloat = 0; shigh = 0; }
    __syncthreads();
    int ff = 0, fh = 0;
    for (int i = threadIdx.x; i < 65536; i += blockDim.x) {
        unsigned int w = m[i];
        if (w == 0x3F800000u) ff = 1;
        else if (w & 0xFFFFFF00u) fh = 1;
    }
    if (ff) atomicOr(&sfloat, 1);
    if (fh) atomicOr(&shigh, 1);
    __syncthreads();
    if (threadIdx.x == 0)
        g_mask_mode = sfloat ? 2 : (shigh ? 1 : 0);
}

// ---------------- mask -> bitmask (1 bit per position) ----------------
__global__ __launch_bounds__(256)
void convert_mask_kernel(const unsigned char* __restrict__ mb)
{
    const int mode = g_mask_mode;
    const int stride = (mode == 1) ? 1 : 4;
    const int offs   = (mode == 2) ? 3 : 0;
    size_t pos = (size_t)blockIdx.x * blockDim.x + threadIdx.x;
    unsigned char v = mb[pos * stride + offs];
    unsigned int bal = __ballot_sync(0xffffffffu, v != 0);
    if ((threadIdx.x & 31) == 0) g_maskbits[pos >> 5] = bal;
}

// ---------------- generic SGEMM: C = A[MxK] @ B[KxN] + bias (+resid) ----------------
__global__ __launch_bounds__(256)
void sgemm_bias(const float* __restrict__ A, const float* __restrict__ B,
                const float* __restrict__ bias, const float* __restrict__ resid,
                float* __restrict__ C, int M, int N, int K)
{
    __shared__ float As[8][128];
    __shared__ float Bs[8][128];
    const int tid   = threadIdx.x;
    const int crow0 = blockIdx.y * 128;
    const int ccol0 = blockIdx.x * 128;
    const int a_row = tid >> 1;
    const int a_col = (tid & 1) << 2;
    const int b_row = tid >> 5;
    const int b_col = (tid & 31) << 2;
    const int tx = tid & 15;
    const int ty = tid >> 4;

    float acc[8][8];
#pragma unroll
    for (int i = 0; i < 8; i++)
#pragma unroll
        for (int j = 0; j < 8; j++) acc[i][j] = 0.f;

    const float* Aptr = A + (size_t)crow0 * K;
    const float* Bptr = B + ccol0;

    for (int k0 = 0; k0 < K; k0 += 8) {
        float4 av = *(const float4*)(Aptr + (size_t)a_row * K + k0 + a_col);
        As[a_col + 0][a_row] = av.x;
        As[a_col + 1][a_row] = av.y;
        As[a_col + 2][a_row] = av.z;
        As[a_col + 3][a_row] = av.w;
        float4 bv = *(const float4*)(Bptr + (size_t)(k0 + b_row) * N + b_col);
        *(float4*)&Bs[b_row][b_col] = bv;
        __syncthreads();
#pragma unroll
        for (int kk = 0; kk < 8; kk++) {
            float ra[8], rb[8];
#pragma unroll
            for (int i = 0; i < 8; i++) ra[i] = As[kk][ty * 8 + i];
#pragma unroll
            for (int j = 0; j < 8; j++) rb[j] = Bs[kk][tx * 8 + j];
#pragma unroll
            for (int i = 0; i < 8; i++)
#pragma unroll
                for (int j = 0; j < 8; j++)
                    acc[i][j] = fmaf(ra[i], rb[j], acc[i][j]);
        }
        __syncthreads();
    }

    const int crow = crow0 + ty * 8;
    const int ccol = ccol0 + tx * 8;
#pragma unroll
    for (int i = 0; i < 8; i++) {
#pragma unroll
        for (int j0 = 0; j0 < 8; j0 += 4) {
            float4 v;
            v.x = acc[i][j0 + 0] + bias[ccol + j0 + 0];
            v.y = acc[i][j0 + 1] + bias[ccol + j0 + 1];
            v.z = acc[i][j0 + 2] + bias[ccol + j0 + 2];
            v.w = acc[i][j0 + 3] + bias[ccol + j0 + 3];
            if (resid) {
                float4 rv = *(const float4*)(resid + (size_t)(crow + i) * N + ccol + j0);
                v.x += rv.x; v.y += rv.y; v.z += rv.z; v.w += rv.w;
            }
            *(float4*)(C + (size_t)(crow + i) * N + ccol + j0) = v;
        }
    }
}

// ---------------- flash-style attention ----------------
// grid: (S/64, B*H), 256 threads. Each block: 64 queries x full head.
// thread t: r = t>>2 (query row), c = t&3 (quarter of key cols / d cols).
__global__ __launch_bounds__(256)
void attn_kernel(const float* __restrict__ qkv,
                 float* __restrict__ out)
{
    extern __shared__ float sm[];
    float (*Qs)[68] = (float(*)[68])(sm);
    float (*Ks)[68] = (float(*)[68])(sm + 64 * 68);
    float (*Vs)[68] = (float(*)[68])(sm + 2 * 64 * 68);
    float (*Ps)[68] = (float(*)[68])(sm + 3 * 64 * 68);
    unsigned long long* Ms64 = (unsigned long long*)(sm + 4 * 64 * 68);

    const int tid = threadIdx.x;
    const int b  = blockIdx.y >> 4;
    const int h  = blockIdx.y & 15;
    const int q0 = blockIdx.x << 6;
    const int r  = tid >> 2;
    const int c  = tid & 3;

    // load Q tile [64 x 64]
    const float* qbase = qkv + (size_t)(b * SS + q0) * 3072 + h * 64;
    for (int i = tid; i < 64 * 16; i += 256) {
        int row = i >> 4, d = (i & 15) << 2;
        float4 v = *(const float4*)(qbase + (size_t)row * 3072 + d);
        Qs[row][d] = v.x; Qs[row][d + 1] = v.y; Qs[row][d + 2] = v.z; Qs[row][d + 3] = v.w;
    }

    float m = -INFINITY, l = 0.f;
    float o[16];
#pragma unroll
    for (int i = 0; i < 16; i++) o[i] = 0.f;

    for (int k0 = 0; k0 < SS; k0 += 64) {
        __syncthreads();   // prior PV reads of Vs/Ps done
        const float* kbase = qkv + (size_t)(b * SS + k0) * 3072 + 1024 + h * 64;
        for (int i = tid; i < 64 * 16; i += 256) {
            int row = i >> 4, d = (i & 15) << 2;
            float4 kv = *(const float4*)(kbase + (size_t)row * 3072 + d);
            Ks[row][d] = kv.x; Ks[row][d + 1] = kv.y; Ks[row][d + 2] = kv.z; Ks[row][d + 3] = kv.w;
            float4 vv = *(const float4*)(kbase + 1024 + (size_t)row * 3072 + d);
            Vs[row][d] = vv.x; Vs[row][d + 1] = vv.y; Vs[row][d + 2] = vv.z; Vs[row][d + 3] = vv.w;
        }
        if (tid < 64) {
            size_t wbase = ((size_t)(b * SS + q0 + tid) * SS + k0) >> 5;
            Ms64[tid] = *(const unsigned long long*)&g_maskbits[wbase];
        }
        __syncthreads();

        // S = Q K^T : thread handles key cols j = c + 4*jj (bank-conflict-free)
        float s[16];
#pragma unroll
        for (int jj = 0; jj < 16; jj++) s[jj] = 0.f;
#pragma unroll
        for (int d0 = 0; d0 < 64; d0 += 4) {
            float4 q4 = *(const float4*)&Qs[r][d0];
#pragma unroll
            for (int jj = 0; jj < 16; jj++) {
                float4 k4 = *(const float4*)&Ks[c + (jj << 2)][d0];
                s[jj] = fmaf(q4.x, k4.x,
                        fmaf(q4.y, k4.y,
                        fmaf(q4.z, k4.z,
                        fmaf(q4.w, k4.w, s[jj]))));
            }
        }

        // mask + scale, tile max
        const unsigned long long mw = Ms64[r];
        float mt = -INFINITY;
#pragma unroll
        for (int jj = 0; jj < 16; jj++) {
            s[jj] = ((mw >> (c + (jj << 2))) & 1ull) ? -1e9f : s[jj] * 0.125f;
            mt = fmaxf(mt, s[jj]);
        }
        mt = fmaxf(mt, __shfl_xor_sync(0xffffffffu, mt, 1));
        mt = fmaxf(mt, __shfl_xor_sync(0xffffffffu, mt, 2));
        float m_new = fmaxf(m, mt);
        float corr = __expf(m - m_new);

        float lsum = 0.f;
#pragma unroll
        for (int jj = 0; jj < 16; jj++) {
            s[jj] = __expf(s[jj] - m_new);
            lsum += s[jj];
        }
        lsum += __shfl_xor_sync(0xffffffffu, lsum, 1);
        lsum += __shfl_xor_sync(0xffffffffu, lsum, 2);
        l = l * corr + lsum;
        m = m_new;
#pragma unroll
        for (int i = 0; i < 16; i++) o[i] *= corr;
#pragma unroll
        for (int jj = 0; jj < 16; jj++) Ps[r][c + (jj << 2)] = s[jj];
        __syncthreads();

        // O += P @ V : thread owns d cols [c*16, c*16+16)
#pragma unroll 8
        for (int j = 0; j < 64; j++) {
            float pv = Ps[r][j];
            const float* vrow = &Vs[j][c << 4];
            float4 v0 = *(const float4*)(vrow);
            float4 v1 = *(const float4*)(vrow + 4);
            float4 v2 = *(const float4*)(vrow + 8);
            float4 v3 = *(const float4*)(vrow + 12);
            o[0]  = fmaf(pv, v0.x, o[0]);  o[1]  = fmaf(pv, v0.y, o[1]);
            o[2]  = fmaf(pv, v0.z, o[2]);  o[3]  = fmaf(pv, v0.w, o[3]);
            o[4]  = fmaf(pv, v1.x, o[4]);  o[5]  = fmaf(pv, v1.y, o[5]);
            o[6]  = fmaf(pv, v1.z, o[6]);  o[7]  = fmaf(pv, v1.w, o[7]);
            o[8]  = fmaf(pv, v2.x, o[8]);  o[9]  = fmaf(pv, v2.y, o[9]);
            o[10] = fmaf(pv, v2.z, o[10]); o[11] = fmaf(pv, v2.w, o[11]);
            o[12] = fmaf(pv, v3.x, o[12]); o[13] = fmaf(pv, v3.y, o[13]);
            o[14] = fmaf(pv, v3.z, o[14]); o[15] = fmaf(pv, v3.w, o[15]);
        }
    }

    float invl = 1.0f / l;
    float* obase = out + (size_t)(b * SS + q0 + r) * 1024 + h * 64 + (c << 4);
#pragma unroll
    for (int j0 = 0; j0 < 16; j0 += 4) {
        float4 v;
        v.x = o[j0 + 0] * invl; v.y = o[j0 + 1] * invl;
        v.z = o[j0 + 2] * invl; v.w = o[j0 + 3] * invl;
        *(float4*)(obase + j0) = v;
    }
}

// ---------------- LayerNorm: one block per row ----------------
__global__ __launch_bounds__(256)
void ln_kernel(const float* __restrict__ y, const float* __restrict__ gam,
               const float* __restrict__ bet, float* __restrict__ out)
{
    const int row = blockIdx.x;
    const int tid = threadIdx.x;
    const float* yr = y + (size_t)row * 1024;
    float4 v = *(const float4*)(yr + (tid << 2));
    float s  = v.x + v.y + v.z + v.w;
    float ss = v.x * v.x + v.y * v.y + v.z * v.z + v.w * v.w;
#pragma unroll
    for (int off = 16; off; off >>= 1) {
        s  += __shfl_xor_sync(0xffffffffu, s,  off);
        ss += __shfl_xor_sync(0xffffffffu, ss, off);
    }
    __shared__ float red[16];
    __shared__ float stats[2];
    const int w = tid >> 5;
    if ((tid & 31) == 0) { red[w] = s; red[w + 8] = ss; }
    __syncthreads();
    if (tid == 0) {
        float ts = 0.f, tss = 0.f;
        for (int i = 0; i < 8; i++) { ts += red[i]; tss += red[i + 8]; }
        float mu  = ts * (1.0f / 1024.0f);
        float var = tss * (1.0f / 1024.0f) - mu * mu;
        stats[0] = mu;
        stats[1] = rsqrtf(var + 1e-5f);
    }
    __syncthreads();
    const float mu = stats[0], inv = stats[1];
    float4 g4 = *(const float4*)(gam + (tid << 2));
    float4 b4 = *(const float4*)(bet + (tid << 2));
    float4 rres;
    rres.x = (v.x - mu) * inv * g4.x + b4.x;
    rres.y = (v.y - mu) * inv * g4.y + b4.y;
    rres.z = (v.z - mu) * inv * g4.z + b4.z;
    rres.w = (v.w - mu) * inv * g4.w + b4.w;
    *(float4*)(out + (size_t)row * 1024 + (tid << 2)) = rres;
}

// ---------------- launch ----------------
extern "C" void kernel_launch(void* const* d_in, const int* in_sizes, int n_in,
                              void* d_out, int out_size)
{
    const float* x      = (const float*)d_in[0];
    const float* W_attn = (const float*)d_in[1];
    const float* b_attn = (const float*)d_in[2];
    const float* W_out  = (const float*)d_in[3];
    const float* b_out  = (const float*)d_in[4];
    const float* ln_g   = (const float*)d_in[5];
    const float* ln_b   = (const float*)d_in[6];
    const unsigned char* mask = (const unsigned char*)d_in[7];
    float* out = (float*)d_out;

    float *qkv, *attn, *y;
    cudaGetSymbolAddress((void**)&qkv,  g_qkv);
    cudaGetSymbolAddress((void**)&attn, g_attn);
    cudaGetSymbolAddress((void**)&y,    g_y);

    // 0) detect mask dtype + pack to bits
    detect_mask_kernel<<<1, 1024>>>((const unsigned int*)mask);
    convert_mask_kernel<<<(BB * SS * SS) / 256, 256>>>(mask);

    // 1) QKV projection: [4096,1024] @ [1024,3072] + b_attn
    dim3 g1(3072 / 128, MROWS / 128);
    sgemm_bias<<<g1, 256>>>(x, W_attn, b_attn, nullptr, qkv, MROWS, 3072, 1024);

    // 2) attention
    const int ATTN_SMEM = 4 * 64 * 68 * (int)sizeof(float) + 64 * 8;  // 70144 B
    cudaFuncSetAttribute(attn_kernel, cudaFuncAttributeMaxDynamicSharedMemorySize, ATTN_SMEM);
    dim3 g2(SS / 64, BB * HH);
    attn_kernel<<<g2, 256, ATTN_SMEM>>>(qkv, attn);

    // 3) out projection + residual: x + attn @ W_out + b_out
    dim3 g3(DD / 128, MROWS / 128);
    sgemm_bias<<<g3, 256>>>(attn, W_out, b_out, x, y, MROWS, DD, DD);

    // 4) LayerNorm
    ln_kernel<<<MROWS, 256>>>(y, ln_g, ln_b, out);
}

// round 3
// speedup vs baseline: 1.1627x; 1.1627x over previous
#include <cuda_runtime.h>
#include <cuda_bf16.h>
#include <math.h>
#include <stdint.h>

#define BB 2
#define SS 2048
#define DD 1024
#define HH 16
#define MROWS (BB*SS)   // 4096
#define KP 3072         // 3*K split depth

// ---------------- scratch (no cudaMalloc allowed) ----------------
__device__ float g_qkv[(size_t)MROWS * 3072];
__device__ float g_attn[(size_t)MROWS * DD];
__device__ float g_y[(size_t)MROWS * DD];
__device__ int   g_mask_mode;
__device__ __align__(8) unsigned int g_maskbits[(size_t)BB * SS * SS / 32];
// bf16x3 operands
__device__ __nv_bfloat16 g_x3[(size_t)MROWS * KP];     // [4096 x 3072]
__device__ __nv_bfloat16 g_at3[(size_t)MROWS * KP];    // [4096 x 3072]
__device__ __nv_bfloat16 g_wa3[(size_t)KP * 3072];     // [3072 x 3072]
__device__ __nv_bfloat16 g_wo3[(size_t)KP * 1024];     // [3072 x 1024]

// ---------------- mask dtype detection ----------------
__global__ void detect_mask_kernel(const unsigned int* __restrict__ m)
{
    __shared__ int sfloat, shigh;
    if (threadIdx.x == 0) { sfloat = 0; shigh = 0; }
    __syncthreads();
    int ff = 0, fh = 0;
    for (int i = threadIdx.x; i < 65536; i += blockDim.x) {
        unsigned int w = m[i];
        if (w == 0x3F800000u) ff = 1;
        else if (w & 0xFFFFFF00u) fh = 1;
    }
    if (ff) atomicOr(&sfloat, 1);
    if (fh) atomicOr(&shigh, 1);
    __syncthreads();
    if (threadIdx.x == 0)
        g_mask_mode = sfloat ? 2 : (shigh ? 1 : 0);
}

__global__ __launch_bounds__(256)
void convert_mask_kernel(const unsigned char* __restrict__ mb)
{
    const int mode = g_mask_mode;
    const int stride = (mode == 1) ? 1 : 4;
    const int offs   = (mode == 2) ? 3 : 0;
    size_t pos = (size_t)blockIdx.x * blockDim.x + threadIdx.x;
    unsigned char v = mb[pos * stride + offs];
    unsigned int bal = __ballot_sync(0xffffffffu, v != 0);
    if ((threadIdx.x & 31) == 0) g_maskbits[pos >> 5] = bal;
}

// ---------------- fp32 -> bf16x3 split conversions ----------------
// A' = [hi | lo | hi] along K  (pairs with B' = [hi ; hi ; lo])
__global__ __launch_bounds__(256)
void cvt_A3(const float* __restrict__ A, __nv_bfloat16* __restrict__ out, int K)
{
    size_t i = ((size_t)blockIdx.x * 256 + threadIdx.x) * 4;
    int m = (int)(i / K), k = (int)(i % K);
    float4 v = *(const float4*)(A + i);
    __nv_bfloat16 h[4], l[4];
    h[0] = __float2bfloat16_rn(v.x); l[0] = __float2bfloat16_rn(v.x - __bfloat162float(h[0]));
    h[1] = __float2bfloat16_rn(v.y); l[1] = __float2bfloat16_rn(v.y - __bfloat162float(h[1]));
    h[2] = __float2bfloat16_rn(v.z); l[2] = __float2bfloat16_rn(v.z - __bfloat162float(h[2]));
    h[3] = __float2bfloat16_rn(v.w); l[3] = __float2bfloat16_rn(v.w - __bfloat162float(h[3]));
    __nv_bfloat16* row = out + (size_t)m * (3 * K);
    *(uint2*)(row + k)         = *(uint2*)h;
    *(uint2*)(row + K + k)     = *(uint2*)l;
    *(uint2*)(row + 2 * K + k) = *(uint2*)h;
}

// B' rows: [0,K)=hi, [K,2K)=hi, [2K,3K)=lo ; B is [K x N] row-major
__global__ __launch_bounds__(256)
void cvt_B3(const float* __restrict__ B, __nv_bfloat16* __restrict__ out, int K, int N)
{
    size_t i = ((size_t)blockIdx.x * 256 + threadIdx.x) * 4;
    if (i >= (size_t)K * N) return;
    int r = (int)(i / N), c = (int)(i % N);
    float4 v = *(const float4*)(B + i);
    __nv_bfloat16 h[4], l[4];
    h[0] = __float2bfloat16_rn(v.x); l[0] = __float2bfloat16_rn(v.x - __bfloat162float(h[0]));
    h[1] = __float2bfloat16_rn(v.y); l[1] = __float2bfloat16_rn(v.y - __bfloat162float(h[1]));
    h[2] = __float2bfloat16_rn(v.z); l[2] = __float2bfloat16_rn(v.z - __bfloat162float(h[2]));
    h[3] = __float2bfloat16_rn(v.w); l[3] = __float2bfloat16_rn(v.w - __bfloat162float(h[3]));
    *(uint2*)(out + (size_t)r * N + c)           = *(uint2*)h;
    *(uint2*)(out + (size_t)(K + r) * N + c)     = *(uint2*)h;
    *(uint2*)(out + (size_t)(2 * K + r) * N + c) = *(uint2*)l;
}

// ---------------- bf16 tensor-core GEMM ----------------
// C[M x N] = A'[M x Kp] @ B'[Kp x N] + bias (+resid), fp32 out.
// block tile 128x128x32, 8 warps (4 along M x 2 along N), warp tile 32x64.
#define LDMX4(R0,R1,R2,R3,addr) \
    asm volatile("ldmatrix.sync.aligned.m8n8.x4.shared.b16 {%0,%1,%2,%3}, [%4];" \
        : "=r"(R0),"=r"(R1),"=r"(R2),"=r"(R3) : "r"(addr))
#define LDMX4T(R0,R1,R2,R3,addr) \
    asm volatile("ldmatrix.sync.aligned.m8n8.x4.trans.shared.b16 {%0,%1,%2,%3}, [%4];" \
        : "=r"(R0),"=r"(R1),"=r"(R2),"=r"(R3) : "r"(addr))
#define MMA16816(d, a, b0, b1) \
    asm volatile("mma.sync.aligned.m16n8k16.row.col.f32.bf16.bf16.f32 " \
        "{%0,%1,%2,%3}, {%4,%5,%6,%7}, {%8,%9}, {%0,%1,%2,%3};" \
        : "+f"(d[0]),"+f"(d[1]),"+f"(d[2]),"+f"(d[3]) \
        : "r"(a[0]),"r"(a[1]),"r"(a[2]),"r"(a[3]), "r"(b0),"r"(b1))

__global__ __launch_bounds__(256)
void gemm_bf16(const __nv_bfloat16* __restrict__ A, const __nv_bfloat16* __restrict__ B,
               const float* __restrict__ bias, const float* __restrict__ resid,
               float* __restrict__ C, int M, int N, int Kp)
{
    __shared__ __align__(16) __nv_bfloat16 As[128][40];   // 80B rows (pad)
    __shared__ __align__(16) __nv_bfloat16 Bs[32][136];   // 272B rows (pad)

    const int tid  = threadIdx.x;
    const int lane = tid & 31;
    const int wid  = tid >> 5;
    const int wm   = wid & 3;    // warp row (x32)
    const int wn   = wid >> 2;   // warp col (x64)
    const int bm = blockIdx.y * 128, bn = blockIdx.x * 128;

    // gmem tile load mapping
    const int a_chunk = tid & 3;       // 4 chunks of 8 bf16 along K(32)
    const int a_row   = tid >> 2;      // 64 rows, two passes
    const int b_chunk = tid & 15;      // 16 chunks of 8 bf16 along N(128)
    const int b_row   = tid >> 4;      // 16 rows, two passes

    const __nv_bfloat16* Ag = A + (size_t)bm * Kp;
    const __nv_bfloat16* Bg = B + bn;

    uint4 ar0, ar1, br0, br1;
    ar0 = *(const uint4*)(Ag + (size_t)a_row * Kp + a_chunk * 8);
    ar1 = *(const uint4*)(Ag + (size_t)(a_row + 64) * Kp + a_chunk * 8);
    br0 = *(const uint4*)(Bg + (size_t)b_row * N + b_chunk * 8);
    br1 = *(const uint4*)(Bg + (size_t)(b_row + 16) * N + b_chunk * 8);

    float acc[2][8][4];
#pragma unroll
    for (int i = 0; i < 2; i++)
#pragma unroll
        for (int j = 0; j < 8; j++)
#pragma unroll
            for (int t = 0; t < 4; t++) acc[i][j][t] = 0.f;

    // ldmatrix base addresses (byte offsets added per kk)
    uint32_t a_base[2], b_base[4];
#pragma unroll
    for (int mi = 0; mi < 2; mi++)
        a_base[mi] = (uint32_t)__cvta_generic_to_shared(
            &As[wm * 32 + mi * 16 + (lane & 15)][(lane >> 4) * 8]);
#pragma unroll
    for (int nc = 0; nc < 4; nc++)
        b_base[nc] = (uint32_t)__cvta_generic_to_shared(
            &Bs[lane & 15][wn * 64 + nc * 16 + (lane >> 4) * 8]);

    for (int k0 = 0; k0 < Kp; k0 += 32) {
        __syncthreads();
        *(uint4*)&As[a_row][a_chunk * 8]       = ar0;
        *(uint4*)&As[a_row + 64][a_chunk * 8]  = ar1;
        *(uint4*)&Bs[b_row][b_chunk * 8]       = br0;
        *(uint4*)&Bs[b_row + 16][b_chunk * 8]  = br1;
        __syncthreads();

        if (k0 + 32 < Kp) {
            const __nv_bfloat16* Ag2 = Ag + k0 + 32;
            const __nv_bfloat16* Bg2 = Bg + (size_t)(k0 + 32) * N;
            ar0 = *(const uint4*)(Ag2 + (size_t)a_row * Kp + a_chunk * 8);
            ar1 = *(const uint4*)(Ag2 + (size_t)(a_row + 64) * Kp + a_chunk * 8);
            br0 = *(const uint4*)(Bg2 + (size_t)b_row * N + b_chunk * 8);
            br1 = *(const uint4*)(Bg2 + (size_t)(b_row + 16) * N + b_chunk * 8);
        }

#pragma unroll
        for (int kk = 0; kk < 2; kk++) {
            uint32_t af[2][4], bf[4][4];
#pragma unroll
            for (int mi = 0; mi < 2; mi++)
                LDMX4(af[mi][0], af[mi][1], af[mi][2], af[mi][3],
                      a_base[mi] + kk * 32);              // +16 bf16 = 32B along row
#pragma unroll
            for (int nc = 0; nc < 4; nc++)
                LDMX4T(bf[nc][0], bf[nc][1], bf[nc][2], bf[nc][3],
                       b_base[nc] + kk * 16 * 272);       // +16 rows of 272B
#pragma unroll
            for (int mi = 0; mi < 2; mi++)
#pragma unroll
                for (int nc = 0; nc < 4; nc++) {
                    MMA16816(acc[mi][nc * 2 + 0], af[mi], bf[nc][0], bf[nc][1]);
                    MMA16816(acc[mi][nc * 2 + 1], af[mi], bf[nc][2], bf[nc][3]);
                }
        }
    }

    // epilogue
    const int row_base = bm + wm * 32 + (lane >> 2);
    const int col_base = bn + wn * 64 + (lane & 3) * 2;
#pragma unroll
    for (int mi = 0; mi < 2; mi++) {
#pragma unroll
        for (int ni = 0; ni < 8; ni++) {
            const int c  = col_base + ni * 8;
            const int r0 = row_base + mi * 16;
            const float bx = bias[c], by = bias[c + 1];
            float2 v0 = make_float2(acc[mi][ni][0] + bx, acc[mi][ni][1] + by);
            float2 v1 = make_float2(acc[mi][ni][2] + bx, acc[mi][ni][3] + by);
            if (resid) {
                float2 r0v = *(const float2*)(resid + (size_t)r0 * N + c);
                float2 r1v = *(const float2*)(resid + (size_t)(r0 + 8) * N + c);
                v0.x += r0v.x; v0.y += r0v.y;
                v1.x += r1v.x; v1.y += r1v.y;
            }
            *(float2*)(C + (size_t)r0 * N + c)       = v0;
            *(float2*)(C + (size_t)(r0 + 8) * N + c) = v1;
        }
    }
}

// ---------------- flash-style attention (unchanged, fp32) ----------------
__global__ __launch_bounds__(256)
void attn_kernel(const float* __restrict__ qkv,
                 float* __restrict__ out)
{
    extern __shared__ float sm[];
    float (*Qs)[68] = (float(*)[68])(sm);
    float (*Ks)[68] = (float(*)[68])(sm + 64 * 68);
    float (*Vs)[68] = (float(*)[68])(sm + 2 * 64 * 68);
    float (*Ps)[68] = (float(*)[68])(sm + 3 * 64 * 68);
    unsigned long long* Ms64 = (unsigned long long*)(sm + 4 * 64 * 68);

    const int tid = threadIdx.x;
    const int b  = blockIdx.y >> 4;
    const int h  = blockIdx.y & 15;
    const int q0 = blockIdx.x << 6;
    const int r  = tid >> 2;
    const int c  = tid & 3;

    const float* qbase = qkv + (size_t)(b * SS + q0) * 3072 + h * 64;
    for (int i = tid; i < 64 * 16; i += 256) {
        int row = i >> 4, d = (i & 15) << 2;
        float4 v = *(const float4*)(qbase + (size_t)row * 3072 + d);
        Qs[row][d] = v.x; Qs[row][d + 1] = v.y; Qs[row][d + 2] = v.z; Qs[row][d + 3] = v.w;
    }

    float m = -INFINITY, l = 0.f;
    float o[16];
#pragma unroll
    for (int i = 0; i < 16; i++) o[i] = 0.f;

    for (int k0 = 0; k0 < SS; k0 += 64) {
        __syncthreads();
        const float* kbase = qkv + (size_t)(b * SS + k0) * 3072 + 1024 + h * 64;
        for (int i = tid; i < 64 * 16; i += 256) {
            int row = i >> 4, d = (i & 15) << 2;
            float4 kv = *(const float4*)(kbase + (size_t)row * 3072 + d);
            Ks[row][d] = kv.x; Ks[row][d + 1] = kv.y; Ks[row][d + 2] = kv.z; Ks[row][d + 3] = kv.w;
            float4 vv = *(const float4*)(kbase + 1024 + (size_t)row * 3072 + d);
            Vs[row][d] = vv.x; Vs[row][d + 1] = vv.y; Vs[row][d + 2] = vv.z; Vs[row][d + 3] = vv.w;
        }
        if (tid < 64) {
            size_t wbase = ((size_t)(b * SS + q0 + tid) * SS + k0) >> 5;
            Ms64[tid] = *(const unsigned long long*)&g_maskbits[wbase];
        }
        __syncthreads();

        float s[16];
#pragma unroll
        for (int jj = 0; jj < 16; jj++) s[jj] = 0.f;
#pragma unroll
        for (int d0 = 0; d0 < 64; d0 += 4) {
            float4 q4 = *(const float4*)&Qs[r][d0];
#pragma unroll
            for (int jj = 0; jj < 16; jj++) {
                float4 k4 = *(const float4*)&Ks[c + (jj << 2)][d0];
                s[jj] = fmaf(q4.x, k4.x,
                        fmaf(q4.y, k4.y,
                        fmaf(q4.z, k4.z,
                        fmaf(q4.w, k4.w, s[jj]))));
            }
        }

        const unsigned long long mw = Ms64[r];
        float mt = -INFINITY;
#pragma unroll
        for (int jj = 0; jj < 16; jj++) {
            s[jj] = ((mw >> (c + (jj << 2))) & 1ull) ? -1e9f : s[jj] * 0.125f;
            mt = fmaxf(mt, s[jj]);
        }
        mt = fmaxf(mt, __shfl_xor_sync(0xffffffffu, mt, 1));
        mt = fmaxf(mt, __shfl_xor_sync(0xffffffffu, mt, 2));
        float m_new = fmaxf(m, mt);
        float corr = __expf(m - m_new);

        float lsum = 0.f;
#pragma unroll
        for (int jj = 0; jj < 16; jj++) {
            s[jj] = __expf(s[jj] - m_new);
            lsum += s[jj];
        }
        lsum += __shfl_xor_sync(0xffffffffu, lsum, 1);
        lsum += __shfl_xor_sync(0xffffffffu, lsum, 2);
        l = l * corr + lsum;
        m = m_new;
#pragma unroll
        for (int i = 0; i < 16; i++) o[i] *= corr;
#pragma unroll
        for (int jj = 0; jj < 16; jj++) Ps[r][c + (jj << 2)] = s[jj];
        __syncthreads();

#pragma unroll 8
        for (int j = 0; j < 64; j++) {
            float pv = Ps[r][j];
            const float* vrow = &Vs[j][c << 4];
            float4 v0 = *(const float4*)(vrow);
            float4 v1 = *(const float4*)(vrow + 4);
            float4 v2 = *(const float4*)(vrow + 8);
            float4 v3 = *(const float4*)(vrow + 12);
            o[0]  = fmaf(pv, v0.x, o[0]);  o[1]  = fmaf(pv, v0.y, o[1]);
            o[2]  = fmaf(pv, v0.z, o[2]);  o[3]  = fmaf(pv, v0.w, o[3]);
            o[4]  = fmaf(pv, v1.x, o[4]);  o[5]  = fmaf(pv, v1.y, o[5]);
            o[6]  = fmaf(pv, v1.z, o[6]);  o[7]  = fmaf(pv, v1.w, o[7]);
            o[8]  = fmaf(pv, v2.x, o[8]);  o[9]  = fmaf(pv, v2.y, o[9]);
            o[10] = fmaf(pv, v2.z, o[10]); o[11] = fmaf(pv, v2.w, o[11]);
            o[12] = fmaf(pv, v3.x, o[12]); o[13] = fmaf(pv, v3.y, o[13]);
            o[14] = fmaf(pv, v3.z, o[14]); o[15] = fmaf(pv, v3.w, o[15]);
        }
    }

    float invl = 1.0f / l;
    float* obase = out + (size_t)(b * SS + q0 + r) * 1024 + h * 64 + (c << 4);
#pragma unroll
    for (int j0 = 0; j0 < 16; j0 += 4) {
        float4 v;
        v.x = o[j0 + 0] * invl; v.y = o[j0 + 1] * invl;
        v.z = o[j0 + 2] * invl; v.w = o[j0 + 3] * invl;
        *(float4*)(obase + j0) = v;
    }
}

// ---------------- LayerNorm ----------------
__global__ __launch_bounds__(256)
void ln_kernel(const float* __restrict__ y, const float* __restrict__ gam,
               const float* __restrict__ bet, float* __restrict__ out)
{
    const int row = blockIdx.x;
    const int tid = threadIdx.x;
    const float* yr = y + (size_t)row * 1024;
    float4 v = *(const float4*)(yr + (tid << 2));
    float s  = v.x + v.y + v.z + v.w;
    float ss = v.x * v.x + v.y * v.y + v.z * v.z + v.w * v.w;
#pragma unroll
    for (int off = 16; off; off >>= 1) {
        s  += __shfl_xor_sync(0xffffffffu, s,  off);
        ss += __shfl_xor_sync(0xffffffffu, ss, off);
    }
    __shared__ float red[16];
    __shared__ float stats[2];
    const int w = tid >> 5;
    if ((tid & 31) == 0) { red[w] = s; red[w + 8] = ss; }
    __syncthreads();
    if (tid == 0) {
        float ts = 0.f, tss = 0.f;
        for (int i = 0; i < 8; i++) { ts += red[i]; tss += red[i + 8]; }
        float mu  = ts * (1.0f / 1024.0f);
        float var = tss * (1.0f / 1024.0f) - mu * mu;
        stats[0] = mu;
        stats[1] = rsqrtf(var + 1e-5f);
    }
    __syncthreads();
    const float mu = stats[0], inv = stats[1];
    float4 g4 = *(const float4*)(gam + (tid << 2));
    float4 b4 = *(const float4*)(bet + (tid << 2));
    float4 rres;
    rres.x = (v.x - mu) * inv * g4.x + b4.x;
    rres.y = (v.y - mu) * inv * g4.y + b4.y;
    rres.z = (v.z - mu) * inv * g4.z + b4.z;
    rres.w = (v.w - mu) * inv * g4.w + b4.w;
    *(float4*)(out + (size_t)row * 1024 + (tid << 2)) = rres;
}

// ---------------- launch ----------------
extern "C" void kernel_launch(void* const* d_in, const int* in_sizes, int n_in,
                              void* d_out, int out_size)
{
    const float* x      = (const float*)d_in[0];
    const float* W_attn = (const float*)d_in[1];
    const float* b_attn = (const float*)d_in[2];
    const float* W_out  = (const float*)d_in[3];
    const float* b_out  = (const float*)d_in[4];
    const float* ln_g   = (const float*)d_in[5];
    const float* ln_b   = (const float*)d_in[6];
    const unsigned char* mask = (const unsigned char*)d_in[7];
    float* out = (float*)d_out;

    float *qkv, *attn, *y;
    __nv_bfloat16 *x3, *at3, *wa3, *wo3;
    cudaGetSymbolAddress((void**)&qkv,  g_qkv);
    cudaGetSymbolAddress((void**)&attn, g_attn);
    cudaGetSymbolAddress((void**)&y,    g_y);
    cudaGetSymbolAddress((void**)&x3,   g_x3);
    cudaGetSymbolAddress((void**)&at3,  g_at3);
    cudaGetSymbolAddress((void**)&wa3,  g_wa3);
    cudaGetSymbolAddress((void**)&wo3,  g_wo3);

    // 0) mask pack + operand conversions
    detect_mask_kernel<<<1, 1024>>>((const unsigned int*)mask);
    convert_mask_kernel<<<(BB * SS * SS) / 256, 256>>>(mask);
    cvt_A3<<<(MROWS * 1024) / 1024, 256>>>(x, x3, 1024);
    cvt_B3<<<(1024 * 3072) / 1024, 256>>>(W_attn, wa3, 1024, 3072);
    cvt_B3<<<(1024 * 1024) / 1024, 256>>>(W_out, wo3, 1024, 1024);

    // 1) QKV projection (tensor cores, bf16x3)
    dim3 g1(3072 / 128, MROWS / 128);
    gemm_bf16<<<g1, 256>>>(x3, wa3, b_attn, nullptr, qkv, MROWS, 3072, KP);

    // 2) attention
    const int ATTN_SMEM = 4 * 64 * 68 * (int)sizeof(float) + 64 * 8;
    cudaFuncSetAttribute(attn_kernel, cudaFuncAttributeMaxDynamicSharedMemorySize, ATTN_SMEM);
    dim3 g2(SS / 64, BB * HH);
    attn_kernel<<<g2, 256, ATTN_SMEM>>>(qkv, attn);

    // 3) out projection + residual (tensor cores, bf16x3)
    cvt_A3<<<(MROWS * 1024) / 1024, 256>>>(attn, at3, 1024);
    dim3 g3(DD / 128, MROWS / 128);
    gemm_bf16<<<g3, 256>>>(at3, wo3, b_out, x, y, MROWS, DD, KP);

    // 4) LayerNorm
    ln_kernel<<<MROWS, 256>>>(y, ln_g, ln_b, out);
}

// round 4
// speedup vs baseline: 4.6593x; 4.0074x over previous
#include <cuda_runtime.h>
#include <cuda_bf16.h>
#include <math.h>
#include <stdint.h>

#define BB 2
#define SS 2048
#define DD 1024
#define HH 16
#define MROWS (BB*SS)   // 4096
#define KP 3072         // 3*K split depth

// ---------------- scratch (no cudaMalloc allowed) ----------------
__device__ float g_qkv[(size_t)MROWS * 3072];
__device__ float g_attn[(size_t)MROWS * DD];
__device__ float g_y[(size_t)MROWS * DD];
__device__ int   g_mask_mode;
__device__ __align__(8) unsigned int g_maskbits[(size_t)BB * SS * SS / 32];
// bf16x3 GEMM operands
__device__ __nv_bfloat16 g_x3[(size_t)MROWS * KP];
__device__ __nv_bfloat16 g_at3[(size_t)MROWS * KP];
__device__ __nv_bfloat16 g_wa3[(size_t)KP * 3072];
__device__ __nv_bfloat16 g_wo3[(size_t)KP * 1024];
// per-head split attention operands [B*H*S, 64]
#define HSZ ((size_t)BB * HH * SS * 64)
__device__ __nv_bfloat16 g_Qhi[HSZ], g_Qlo[HSZ];
__device__ __nv_bfloat16 g_Khi[HSZ], g_Klo[HSZ];
__device__ __nv_bfloat16 g_Vhi[HSZ], g_Vlo[HSZ];

// ---------------- mask dtype detection ----------------
__global__ void detect_mask_kernel(const unsigned int* __restrict__ m)
{
    __shared__ int sfloat, shigh;
    if (threadIdx.x == 0) { sfloat = 0; shigh = 0; }
    __syncthreads();
    int ff = 0, fh = 0;
    for (int i = threadIdx.x; i < 65536; i += blockDim.x) {
        unsigned int w = m[i];
        if (w == 0x3F800000u) ff = 1;
        else if (w & 0xFFFFFF00u) fh = 1;
    }
    if (ff) atomicOr(&sfloat, 1);
    if (fh) atomicOr(&shigh, 1);
    __syncthreads();
    if (threadIdx.x == 0)
        g_mask_mode = sfloat ? 2 : (shigh ? 1 : 0);
}

__global__ __launch_bounds__(256)
void convert_mask_kernel(const unsigned char* __restrict__ mb)
{
    const int mode = g_mask_mode;
    const int stride = (mode == 1) ? 1 : 4;
    const int offs   = (mode == 2) ? 3 : 0;
    size_t pos = (size_t)blockIdx.x * blockDim.x + threadIdx.x;
    unsigned char v = mb[pos * stride + offs];
    unsigned int bal = __ballot_sync(0xffffffffu, v != 0);
    if ((threadIdx.x & 31) == 0) g_maskbits[pos >> 5] = bal;
}

// ---------------- fp32 -> bf16x3 split conversions (GEMM operands) ----------------
__global__ __launch_bounds__(256)
void cvt_A3(const float* __restrict__ A, __nv_bfloat16* __restrict__ out, int K)
{
    size_t i = ((size_t)blockIdx.x * 256 + threadIdx.x) * 4;
    int m = (int)(i / K), k = (int)(i % K);
    float4 v = *(const float4*)(A + i);
    __nv_bfloat16 h[4], l[4];
    h[0] = __float2bfloat16_rn(v.x); l[0] = __float2bfloat16_rn(v.x - __bfloat162float(h[0]));
    h[1] = __float2bfloat16_rn(v.y); l[1] = __float2bfloat16_rn(v.y - __bfloat162float(h[1]));
    h[2] = __float2bfloat16_rn(v.z); l[2] = __float2bfloat16_rn(v.z - __bfloat162float(h[2]));
    h[3] = __float2bfloat16_rn(v.w); l[3] = __float2bfloat16_rn(v.w - __bfloat162float(h[3]));
    __nv_bfloat16* row = out + (size_t)m * (3 * K);
    *(uint2*)(row + k)         = *(uint2*)h;
    *(uint2*)(row + K + k)     = *(uint2*)l;
    *(uint2*)(row + 2 * K + k) = *(uint2*)h;
}

__global__ __launch_bounds__(256)
void cvt_B3(const float* __restrict__ B, __nv_bfloat16* __restrict__ out, int K, int N)
{
    size_t i = ((size_t)blockIdx.x * 256 + threadIdx.x) * 4;
    if (i >= (size_t)K * N) return;
    int r = (int)(i / N), c = (int)(i % N);
    float4 v = *(const float4*)(B + i);
    __nv_bfloat16 h[4], l[4];
    h[0] = __float2bfloat16_rn(v.x); l[0] = __float2bfloat16_rn(v.x - __bfloat162float(h[0]));
    h[1] = __float2bfloat16_rn(v.y); l[1] = __float2bfloat16_rn(v.y - __bfloat162float(h[1]));
    h[2] = __float2bfloat16_rn(v.z); l[2] = __float2bfloat16_rn(v.z - __bfloat162float(h[2]));
    h[3] = __float2bfloat16_rn(v.w); l[3] = __float2bfloat16_rn(v.w - __bfloat162float(h[3]));
    *(uint2*)(out + (size_t)r * N + c)           = *(uint2*)h;
    *(uint2*)(out + (size_t)(K + r) * N + c)     = *(uint2*)h;
    *(uint2*)(out + (size_t)(2 * K + r) * N + c) = *(uint2*)l;
}

// ---------------- qkv fp32 -> per-head bf16 hi/lo arrays ----------------
__global__ __launch_bounds__(256)
void cvt_qkv_split(const float* __restrict__ qkv)
{
    size_t i = ((size_t)blockIdx.x * 256 + threadIdx.x) * 4;
    int row = (int)(i / 3072), col = (int)(i % 3072);
    int sec = col >> 10;           // 0=q,1=k,2=v
    int h   = (col & 1023) >> 6;
    int d   = col & 63;
    int b   = row >> 11, s = row & 2047;
    float4 v = *(const float4*)(qkv + i);
    __nv_bfloat16 hh[4], ll[4];
    hh[0] = __float2bfloat16_rn(v.x); ll[0] = __float2bfloat16_rn(v.x - __bfloat162float(hh[0]));
    hh[1] = __float2bfloat16_rn(v.y); ll[1] = __float2bfloat16_rn(v.y - __bfloat162float(hh[1]));
    hh[2] = __float2bfloat16_rn(v.z); ll[2] = __float2bfloat16_rn(v.z - __bfloat162float(hh[2]));
    hh[3] = __float2bfloat16_rn(v.w); ll[3] = __float2bfloat16_rn(v.w - __bfloat162float(hh[3]));
    size_t dst = (((size_t)(b * HH + h) * SS + s) << 6) + d;
    __nv_bfloat16 *ph, *pl;
    if (sec == 0)      { ph = g_Qhi; pl = g_Qlo; }
    else if (sec == 1) { ph = g_Khi; pl = g_Klo; }
    else               { ph = g_Vhi; pl = g_Vlo; }
    *(uint2*)(ph + dst) = *(uint2*)hh;
    *(uint2*)(pl + dst) = *(uint2*)ll;
}

// ---------------- MMA macros ----------------
#define LDMX4(R0,R1,R2,R3,addr) \
    asm volatile("ldmatrix.sync.aligned.m8n8.x4.shared.b16 {%0,%1,%2,%3}, [%4];" \
        : "=r"(R0),"=r"(R1),"=r"(R2),"=r"(R3) : "r"(addr))
#define LDMX4T(R0,R1,R2,R3,addr) \
    asm volatile("ldmatrix.sync.aligned.m8n8.x4.trans.shared.b16 {%0,%1,%2,%3}, [%4];" \
        : "=r"(R0),"=r"(R1),"=r"(R2),"=r"(R3) : "r"(addr))
#define MMA16816(d, a, b0, b1) \
    asm volatile("mma.sync.aligned.m16n8k16.row.col.f32.bf16.bf16.f32 " \
        "{%0,%1,%2,%3}, {%4,%5,%6,%7}, {%8,%9}, {%0,%1,%2,%3};" \
        : "+f"(d[0]),"+f"(d[1]),"+f"(d[2]),"+f"(d[3]) \
        : "r"(a[0]),"r"(a[1]),"r"(a[2]),"r"(a[3]), "r"(b0),"r"(b1))

__device__ __forceinline__ uint32_t pack_bf2(float a, float b) {
    __nv_bfloat162 t = __floats2bfloat162_rn(a, b);
    return *(uint32_t*)&t;
}

// ---------------- bf16 tensor-core GEMM (unchanged from round 3) ----------------
__global__ __launch_bounds__(256)
void gemm_bf16(const __nv_bfloat16* __restrict__ A, const __nv_bfloat16* __restrict__ B,
               const float* __restrict__ bias, const float* __restrict__ resid,
               float* __restrict__ C, int M, int N, int Kp)
{
    __shared__ __align__(16) __nv_bfloat16 As[128][40];
    __shared__ __align__(16) __nv_bfloat16 Bs[32][136];

    const int tid  = threadIdx.x;
    const int lane = tid & 31;
    const int wid  = tid >> 5;
    const int wm   = wid & 3;
    const int wn   = wid >> 2;
    const int bm = blockIdx.y * 128, bn = blockIdx.x * 128;

    const int a_chunk = tid & 3;
    const int a_row   = tid >> 2;
    const int b_chunk = tid & 15;
    const int b_row   = tid >> 4;

    const __nv_bfloat16* Ag = A + (size_t)bm * Kp;
    const __nv_bfloat16* Bg = B + bn;

    uint4 ar0, ar1, br0, br1;
    ar0 = *(const uint4*)(Ag + (size_t)a_row * Kp + a_chunk * 8);
    ar1 = *(const uint4*)(Ag + (size_t)(a_row + 64) * Kp + a_chunk * 8);
    br0 = *(const uint4*)(Bg + (size_t)b_row * N + b_chunk * 8);
    br1 = *(const uint4*)(Bg + (size_t)(b_row + 16) * N + b_chunk * 8);

    float acc[2][8][4];
#pragma unroll
    for (int i = 0; i < 2; i++)
#pragma unroll
        for (int j = 0; j < 8; j++)
#pragma unroll
            for (int t = 0; t < 4; t++) acc[i][j][t] = 0.f;

    uint32_t a_base[2], b_base[4];
#pragma unroll
    for (int mi = 0; mi < 2; mi++)
        a_base[mi] = (uint32_t)__cvta_generic_to_shared(
            &As[wm * 32 + mi * 16 + (lane & 15)][(lane >> 4) * 8]);
#pragma unroll
    for (int nc = 0; nc < 4; nc++)
        b_base[nc] = (uint32_t)__cvta_generic_to_shared(
            &Bs[lane & 15][wn * 64 + nc * 16 + (lane >> 4) * 8]);

    for (int k0 = 0; k0 < Kp; k0 += 32) {
        __syncthreads();
        *(uint4*)&As[a_row][a_chunk * 8]       = ar0;
        *(uint4*)&As[a_row + 64][a_chunk * 8]  = ar1;
        *(uint4*)&Bs[b_row][b_chunk * 8]       = br0;
        *(uint4*)&Bs[b_row + 16][b_chunk * 8]  = br1;
        __syncthreads();

        if (k0 + 32 < Kp) {
            const __nv_bfloat16* Ag2 = Ag + k0 + 32;
            const __nv_bfloat16* Bg2 = Bg + (size_t)(k0 + 32) * N;
            ar0 = *(const uint4*)(Ag2 + (size_t)a_row * Kp + a_chunk * 8);
            ar1 = *(const uint4*)(Ag2 + (size_t)(a_row + 64) * Kp + a_chunk * 8);
            br0 = *(const uint4*)(Bg2 + (size_t)b_row * N + b_chunk * 8);
            br1 = *(const uint4*)(Bg2 + (size_t)(b_row + 16) * N + b_chunk * 8);
        }

#pragma unroll
        for (int kk = 0; kk < 2; kk++) {
            uint32_t af[2][4], bf[4][4];
#pragma unroll
            for (int mi = 0; mi < 2; mi++)
                LDMX4(af[mi][0], af[mi][1], af[mi][2], af[mi][3],
                      a_base[mi] + kk * 32);
#pragma unroll
            for (int nc = 0; nc < 4; nc++)
                LDMX4T(bf[nc][0], bf[nc][1], bf[nc][2], bf[nc][3],
                       b_base[nc] + kk * 16 * 272);
#pragma unroll
            for (int mi = 0; mi < 2; mi++)
#pragma unroll
                for (int nc = 0; nc < 4; nc++) {
                    MMA16816(acc[mi][nc * 2 + 0], af[mi], bf[nc][0], bf[nc][1]);
                    MMA16816(acc[mi][nc * 2 + 1], af[mi], bf[nc][2], bf[nc][3]);
                }
        }
    }

    const int row_base = bm + wm * 32 + (lane >> 2);
    const int col_base = bn + wn * 64 + (lane & 3) * 2;
#pragma unroll
    for (int mi = 0; mi < 2; mi++) {
#pragma unroll
        for (int ni = 0; ni < 8; ni++) {
            const int c  = col_base + ni * 8;
            const int r0 = row_base + mi * 16;
            const float bx = bias[c], by = bias[c + 1];
            float2 v0 = make_float2(acc[mi][ni][0] + bx, acc[mi][ni][1] + by);
            float2 v1 = make_float2(acc[mi][ni][2] + bx, acc[mi][ni][3] + by);
            if (resid) {
                float2 r0v = *(const float2*)(resid + (size_t)r0 * N + c);
                float2 r1v = *(const float2*)(resid + (size_t)(r0 + 8) * N + c);
                v0.x += r0v.x; v0.y += r0v.y;
                v1.x += r1v.x; v1.y += r1v.y;
            }
            *(float2*)(C + (size_t)r0 * N + c)       = v0;
            *(float2*)(C + (size_t)(r0 + 8) * N + c) = v1;
        }
    }
}

// ---------------- tensor-core flash attention ----------------
// grid (S/64, B*H), 128 threads (4 warps x 16 q-rows).
// smem tiles padded to 136 cols (272B rows).
#define ATTN_PAD 136
#define ROWB (ATTN_PAD*2)   // 272 bytes per row

__global__ __launch_bounds__(128)
void attn_mma(float* __restrict__ out)
{
    extern __shared__ char smc[];
    __nv_bfloat16 (*Qs)[ATTN_PAD] = (__nv_bfloat16(*)[ATTN_PAD])(smc);
    __nv_bfloat16 (*Ks)[ATTN_PAD] = (__nv_bfloat16(*)[ATTN_PAD])(smc + 64 * ROWB);
    __nv_bfloat16 (*Vs)[ATTN_PAD] = (__nv_bfloat16(*)[ATTN_PAD])(smc + 2 * 64 * ROWB);
    __nv_bfloat16 (*Ps)[ATTN_PAD] = (__nv_bfloat16(*)[ATTN_PAD])(smc + 3 * 64 * ROWB);
    unsigned long long* Ms = (unsigned long long*)(smc + 4 * 64 * ROWB);

    const int tid  = threadIdx.x;
    const int lane = tid & 31;
    const int wid  = tid >> 5;
    const int wq   = wid << 4;          // warp q offset within tile
    const int b  = blockIdx.y >> 4;
    const int h  = blockIdx.y & 15;
    const int q0 = blockIdx.x << 6;
    const size_t head_base = ((size_t)(b * HH + h) * SS) << 6;

    // ---- load Q tile (hi -> cols 0-63, lo -> cols 64-127) ----
    for (int i = tid; i < 512; i += 128) {
        int row = i >> 3, seg = (i & 7) << 3;
        size_t g = head_base + (size_t)(q0 + row) * 64 + seg;
        *(uint4*)&Qs[row][seg]      = *(const uint4*)(g_Qhi + g);
        *(uint4*)&Qs[row][64 + seg] = *(const uint4*)(g_Qlo + g);
    }

    // ldmatrix bases
    const uint32_t a_base = (uint32_t)__cvta_generic_to_shared(
        &Qs[wq + (lane & 15)][(lane >> 4) * 8]);
    const int mat = lane >> 3, rr = lane & 7;
    const uint32_t kb_base = (uint32_t)__cvta_generic_to_shared(
        &Ks[((mat >> 1) << 3) + rr][(mat & 1) * 8]);
    const uint32_t vb_base = (uint32_t)__cvta_generic_to_shared(
        &Vs[lane & 15][(lane >> 4) * 8]);
    const uint32_t p_base = (uint32_t)__cvta_generic_to_shared(
        &Ps[wq + (lane & 15)][(lane >> 4) * 8]);

    float oacc[8][4];
#pragma unroll
    for (int i = 0; i < 8; i++)
#pragma unroll
        for (int t = 0; t < 4; t++) oacc[i][t] = 0.f;
    float m0 = -INFINITY, m1 = -INFINITY, l0 = 0.f, l1 = 0.f;

    for (int k0 = 0; k0 < SS; k0 += 64) {
        __syncthreads();
        // ---- load K/V tiles + mask ----
        for (int i = tid; i < 512; i += 128) {
            int row = i >> 3, seg = (i & 7) << 3;
            size_t g = head_base + (size_t)(k0 + row) * 64 + seg;
            *(uint4*)&Ks[row][seg]      = *(const uint4*)(g_Khi + g);
            *(uint4*)&Ks[row][64 + seg] = *(const uint4*)(g_Klo + g);
            *(uint4*)&Vs[row][seg]      = *(const uint4*)(g_Vhi + g);
            *(uint4*)&Vs[row][64 + seg] = *(const uint4*)(g_Vlo + g);
        }
        if (tid < 64) {
            size_t wb = ((size_t)(b * SS + q0 + tid) * SS + k0) >> 5;
            Ms[tid] = *(const unsigned long long*)&g_maskbits[wb];
        }
        __syncthreads();

        // ---- S = Q K^T (3-term split) ----
        float sacc[8][4];
#pragma unroll
        for (int i = 0; i < 8; i++)
#pragma unroll
            for (int t = 0; t < 4; t++) sacc[i][t] = 0.f;

#pragma unroll
        for (int kk = 0; kk < 4; kk++) {
            uint32_t ah[4], al[4];
            LDMX4(ah[0], ah[1], ah[2], ah[3], a_base + kk * 32);
            LDMX4(al[0], al[1], al[2], al[3], a_base + 128 + kk * 32);
#pragma unroll
            for (int g = 0; g < 4; g++) {
                uint32_t kh[4], kl[4];
                LDMX4(kh[0], kh[1], kh[2], kh[3], kb_base + g * (16 * ROWB) + kk * 32);
                MMA16816(sacc[2 * g + 0], ah, kh[0], kh[1]);
                MMA16816(sacc[2 * g + 1], ah, kh[2], kh[3]);
                MMA16816(sacc[2 * g + 0], al, kh[0], kh[1]);
                MMA16816(sacc[2 * g + 1], al, kh[2], kh[3]);
                LDMX4(kl[0], kl[1], kl[2], kl[3], kb_base + 128 + g * (16 * ROWB) + kk * 32);
                MMA16816(sacc[2 * g + 0], ah, kl[0], kl[1]);
                MMA16816(sacc[2 * g + 1], ah, kl[2], kl[3]);
            }
        }

        // ---- scale + mask ----
        const int r0 = wq + (lane >> 2);
        const unsigned long long mw0 = Ms[r0];
        const unsigned long long mw1 = Ms[r0 + 8];
        const int cb0 = (lane & 3) << 1;
#pragma unroll
        for (int nb = 0; nb < 8; nb++) {
            int cb = (nb << 3) + cb0;
            sacc[nb][0] = ((mw0 >> cb) & 1ull)       ? -1e9f : sacc[nb][0] * 0.125f;
            sacc[nb][1] = ((mw0 >> (cb + 1)) & 1ull) ? -1e9f : sacc[nb][1] * 0.125f;
            sacc[nb][2] = ((mw1 >> cb) & 1ull)       ? -1e9f : sacc[nb][2] * 0.125f;
            sacc[nb][3] = ((mw1 >> (cb + 1)) & 1ull) ? -1e9f : sacc[nb][3] * 0.125f;
        }

        // ---- online softmax ----
        float mt0 = -1e30f, mt1 = -1e30f;
#pragma unroll
        for (int nb = 0; nb < 8; nb++) {
            mt0 = fmaxf(mt0, fmaxf(sacc[nb][0], sacc[nb][1]));
            mt1 = fmaxf(mt1, fmaxf(sacc[nb][2], sacc[nb][3]));
        }
        mt0 = fmaxf(mt0, __shfl_xor_sync(0xffffffffu, mt0, 1));
        mt0 = fmaxf(mt0, __shfl_xor_sync(0xffffffffu, mt0, 2));
        mt1 = fmaxf(mt1, __shfl_xor_sync(0xffffffffu, mt1, 1));
        mt1 = fmaxf(mt1, __shfl_xor_sync(0xffffffffu, mt1, 2));
        float mn0 = fmaxf(m0, mt0), mn1 = fmaxf(m1, mt1);
        float c0 = __expf(m0 - mn0), c1 = __expf(m1 - mn1);

        float ls0 = 0.f, ls1 = 0.f;
#pragma unroll
        for (int nb = 0; nb < 8; nb++) {
            sacc[nb][0] = __expf(sacc[nb][0] - mn0);
            sacc[nb][1] = __expf(sacc[nb][1] - mn0);
            sacc[nb][2] = __expf(sacc[nb][2] - mn1);
            sacc[nb][3] = __expf(sacc[nb][3] - mn1);
            ls0 += sacc[nb][0] + sacc[nb][1];
            ls1 += sacc[nb][2] + sacc[nb][3];
        }
        ls0 += __shfl_xor_sync(0xffffffffu, ls0, 1);
        ls0 += __shfl_xor_sync(0xffffffffu, ls0, 2);
        ls1 += __shfl_xor_sync(0xffffffffu, ls1, 1);
        ls1 += __shfl_xor_sync(0xffffffffu, ls1, 2);
        l0 = l0 * c0 + ls0; l1 = l1 * c1 + ls1;
        m0 = mn0; m1 = mn1;
#pragma unroll
        for (int nb = 0; nb < 8; nb++) {
            oacc[nb][0] *= c0; oacc[nb][1] *= c0;
            oacc[nb][2] *= c1; oacc[nb][3] *= c1;
        }

        // ---- write P (hi cols 0-63, lo cols 64-127) ----
#pragma unroll
        for (int nb = 0; nb < 8; nb++) {
            int cb = (nb << 3) + cb0;
            float p00 = sacc[nb][0], p01 = sacc[nb][1];
            float p10 = sacc[nb][2], p11 = sacc[nb][3];
            float h00 = __bfloat162float(__float2bfloat16_rn(p00));
            float h01 = __bfloat162float(__float2bfloat16_rn(p01));
            float h10 = __bfloat162float(__float2bfloat16_rn(p10));
            float h11 = __bfloat162float(__float2bfloat16_rn(p11));
            *(uint32_t*)&Ps[r0][cb]          = pack_bf2(p00, p01);
            *(uint32_t*)&Ps[r0][64 + cb]     = pack_bf2(p00 - h00, p01 - h01);
            *(uint32_t*)&Ps[r0 + 8][cb]      = pack_bf2(p10, p11);
            *(uint32_t*)&Ps[r0 + 8][64 + cb] = pack_bf2(p10 - h10, p11 - h11);
        }
        __syncwarp();

        // ---- O += P V (3-term split) ----
#pragma unroll
        for (int kk = 0; kk < 4; kk++) {
            uint32_t ph[4], pl[4];
            LDMX4(ph[0], ph[1], ph[2], ph[3], p_base + kk * 32);
            LDMX4(pl[0], pl[1], pl[2], pl[3], p_base + 128 + kk * 32);
#pragma unroll
            for (int nc = 0; nc < 4; nc++) {
                uint32_t vh[4], vl[4];
                LDMX4T(vh[0], vh[1], vh[2], vh[3], vb_base + nc * 32 + kk * (16 * ROWB));
                MMA16816(oacc[2 * nc + 0], ph, vh[0], vh[1]);
                MMA16816(oacc[2 * nc + 1], ph, vh[2], vh[3]);
                MMA16816(oacc[2 * nc + 0], pl, vh[0], vh[1]);
                MMA16816(oacc[2 * nc + 1], pl, vh[2], vh[3]);
                LDMX4T(vl[0], vl[1], vl[2], vl[3], vb_base + 128 + nc * 32 + kk * (16 * ROWB));
                MMA16816(oacc[2 * nc + 0], ph, vl[0], vl[1]);
                MMA16816(oacc[2 * nc + 1], ph, vl[2], vl[3]);
            }
        }
    }

    // ---- epilogue ----
    const float i0 = 1.0f / l0, i1 = 1.0f / l1;
    const int grow0 = b * SS + q0 + wq + (lane >> 2);
    const int colb  = h * 64 + ((lane & 3) << 1);
#pragma unroll
    for (int nb = 0; nb < 8; nb++) {
        int c = colb + (nb << 3);
        *(float2*)(out + (size_t)grow0 * DD + c) =
            make_float2(oacc[nb][0] * i0, oacc[nb][1] * i0);
        *(float2*)(out + (size_t)(grow0 + 8) * DD + c) =
            make_float2(oacc[nb][2] * i1, oacc[nb][3] * i1);
    }
}

// ---------------- LayerNorm ----------------
__global__ __launch_bounds__(256)
void ln_kernel(const float* __restrict__ y, const float* __restrict__ gam,
               const float* __restrict__ bet, float* __restrict__ out)
{
    const int row = blockIdx.x;
    const int tid = threadIdx.x;
    const float* yr = y + (size_t)row * 1024;
    float4 v = *(const float4*)(yr + (tid << 2));
    float s  = v.x + v.y + v.z + v.w;
    float ss = v.x * v.x + v.y * v.y + v.z * v.z + v.w * v.w;
#pragma unroll
    for (int off = 16; off; off >>= 1) {
        s  += __shfl_xor_sync(0xffffffffu, s,  off);
        ss += __shfl_xor_sync(0xffffffffu, ss, off);
    }
    __shared__ float red[16];
    __shared__ float stats[2];
    const int w = tid >> 5;
    if ((tid & 31) == 0) { red[w] = s; red[w + 8] = ss; }
    __syncthreads();
    if (tid == 0) {
        float ts = 0.f, tss = 0.f;
        for (int i = 0; i < 8; i++) { ts += red[i]; tss += red[i + 8]; }
        float mu  = ts * (1.0f / 1024.0f);
        float var = tss * (1.0f / 1024.0f) - mu * mu;
        stats[0] = mu;
        stats[1] = rsqrtf(var + 1e-5f);
    }
    __syncthreads();
    const float mu = stats[0], inv = stats[1];
    float4 g4 = *(const float4*)(gam + (tid << 2));
    float4 b4 = *(const float4*)(bet + (tid << 2));
    float4 rres;
    rres.x = (v.x - mu) * inv * g4.x + b4.x;
    rres.y = (v.y - mu) * inv * g4.y + b4.y;
    rres.z = (v.z - mu) * inv * g4.z + b4.z;
    rres.w = (v.w - mu) * inv * g4.w + b4.w;
    *(float4*)(out + (size_t)row * 1024 + (tid << 2)) = rres;
}

// ---------------- launch ----------------
extern "C" void kernel_launch(void* const* d_in, const int* in_sizes, int n_in,
                              void* d_out, int out_size)
{
    const float* x      = (const float*)d_in[0];
    const float* W_attn = (const float*)d_in[1];
    const float* b_attn = (const float*)d_in[2];
    const float* W_out  = (const float*)d_in[3];
    const float* b_out  = (const float*)d_in[4];
    const float* ln_g   = (const float*)d_in[5];
    const float* ln_b   = (const float*)d_in[6];
    const unsigned char* mask = (const unsigned char*)d_in[7];
    float* out = (float*)d_out;

    float *qkv, *attn, *y;
    __nv_bfloat16 *x3, *at3, *wa3, *wo3;
    cudaGetSymbolAddress((void**)&qkv,  g_qkv);
    cudaGetSymbolAddress((void**)&attn, g_attn);
    cudaGetSymbolAddress((void**)&y,    g_y);
    cudaGetSymbolAddress((void**)&x3,   g_x3);
    cudaGetSymbolAddress((void**)&at3,  g_at3);
    cudaGetSymbolAddress((void**)&wa3,  g_wa3);
    cudaGetSymbolAddress((void**)&wo3,  g_wo3);

    // 0) mask pack + operand conversions
    detect_mask_kernel<<<1, 1024>>>((const unsigned int*)mask);
    convert_mask_kernel<<<(BB * SS * SS) / 256, 256>>>(mask);
    cvt_A3<<<(MROWS * 1024) / 1024, 256>>>(x, x3, 1024);
    cvt_B3<<<(1024 * 3072) / 1024, 256>>>(W_attn, wa3, 1024, 3072);
    cvt_B3<<<(1024 * 1024) / 1024, 256>>>(W_out, wo3, 1024, 1024);

    // 1) QKV projection (tensor cores)
    dim3 g1(3072 / 128, MROWS / 128);
    gemm_bf16<<<g1, 256>>>(x3, wa3, b_attn, nullptr, qkv, MROWS, 3072, KP);

    // 1b) split qkv into per-head bf16 hi/lo
    cvt_qkv_split<<<(MROWS * 3072) / 1024, 256>>>(qkv);

    // 2) attention (tensor cores)
    const int ATTN_SMEM = 4 * 64 * ROWB + 64 * 8;   // 70144 B
    cudaFuncSetAttribute(attn_mma, cudaFuncAttributeMaxDynamicSharedMemorySize, ATTN_SMEM);
    dim3 g2(SS / 64, BB * HH);
    attn_mma<<<g2, 128, ATTN_SMEM>>>(attn);

    // 3) out projection + residual (tensor cores)
    cvt_A3<<<(MROWS * 1024) / 1024, 256>>>(attn, at3, 1024);
    dim3 g3(DD / 128, MROWS / 128);
    gemm_bf16<<<g3, 256>>>(at3, wo3, b_out, x, y, MROWS, DD, KP);

    // 4) LayerNorm
    ln_kernel<<<MROWS, 256>>>(y, ln_g, ln_b, out);
}